// round 12
// baseline (speedup 1.0000x reference)
#include <cuda_runtime.h>
#include <cuda_bf16.h>
#include <cstdint>

#define Bsz 64
#define T   256
#define Isz 2048
#define Hsz 4096
#define Osz 1024

#define THRESHOLD 1.0f
#define DECAY     0.9f

// ---------------- scratch (device globals; no allocation allowed) ----------
__device__ __nv_bfloat16 g_Ahi[T * Isz];     // 1 MB
__device__ __nv_bfloat16 g_Alo[T * Isz];     // 1 MB
__device__ __nv_bfloat16 g_Bhi[Hsz * Isz];   // 16 MB  [N=4096][K=2048] K-major
__device__ __nv_bfloat16 g_Blo[Hsz * Isz];   // 16 MB
__device__ float g_cur[T * Hsz];             // 4 MB
__device__ float g_agg[Hsz];
__device__ int   g_flag[32];                 // per-chunk readiness (0-init)
__device__ int   g_done;                     // end-of-kernel reset counter

// ---------------- PTX helpers ----------------------------------------------
__device__ __forceinline__ uint32_t smem_u32(const void* p) {
    uint32_t a;
    asm("{ .reg .u64 t; cvta.to.shared.u64 t, %1; cvt.u32.u64 %0, t; }"
        : "=r"(a) : "l"(p));
    return a;
}
__device__ __forceinline__ void cp16(uint32_t dst, const void* src) {
    asm volatile("cp.async.cg.shared.global [%0], [%1], 16;" :: "r"(dst), "l"(src));
}
__device__ __forceinline__ void cp_commit() {
    asm volatile("cp.async.commit_group;" ::: "memory");
}
template <int N> __device__ __forceinline__ void cp_wait() {
    asm volatile("cp.async.wait_group %0;" :: "n"(N) : "memory");
}
__device__ __forceinline__ int ld_acq(const int* p) {
    int v;
    asm volatile("ld.acquire.gpu.b32 %0, [%1];" : "=r"(v) : "l"(p) : "memory");
    return v;
}
#define LDSM_X4(r0, r1, r2, r3, addr) \
    asm volatile("ldmatrix.sync.aligned.m8n8.x4.shared.b16 {%0,%1,%2,%3}, [%4];" \
                 : "=r"(r0), "=r"(r1), "=r"(r2), "=r"(r3) : "r"(addr))
#define MMA_BF16(d, a, b0, b1) \
    asm volatile("mma.sync.aligned.m16n8k16.row.col.f32.bf16.bf16.f32 " \
                 "{%0,%1,%2,%3}, {%4,%5,%6,%7}, {%8,%9}, {%0,%1,%2,%3};" \
                 : "+f"((d)[0]), "+f"((d)[1]), "+f"((d)[2]), "+f"((d)[3]) \
                 : "r"((a)[0]), "r"((a)[1]), "r"((a)[2]), "r"((a)[3]), \
                   "r"(b0), "r"(b1))

// ---------------------------------------------------------------------------
// Fused prep + HMMA GEMM.
//   Per chunk c each CTA contributes: A share (2 t-rows x 64 i, x reduced over
//   b=64) and B share (64i x 32h W transpose, bf16 hi/lo). Shares staged via
//   cp.async in smem, consumed 1 chunk later, published via g_flag[c].
//   GEMM: acc += Ahi*Bhi + Alo*Bhi + Ahi*Blo, CTA 64x128, 3-stage pipeline.
// ---------------------------------------------------------------------------
#define LDA_B 144
#define A_TILE_B (64 * LDA_B)            // 9216
#define B_TILE_B (128 * LDA_B)           // 18432
#define STAGE_B  (2 * A_TILE_B + 2 * B_TILE_B)  // 55296
#define NSTAGE 3
#define XBUF_OFF (NSTAGE * STAGE_B)      // 165888 (x stage: 32 KB)
#define WBUF_OFF (XBUF_OFF + 32768)      // 198656 (W stage: 64 x 36 floats)
#define FUSED_SMEM (WBUF_OFF + 9216)     // 207872
#define NCHUNK 32

__global__ __launch_bounds__(256, 1) void fused_gemm(
    const float* __restrict__ x, const float* __restrict__ W,
    const float* __restrict__ b_in)
{
    extern __shared__ char smem[];
    const uint32_t sb = smem_u32(smem);
    const int tid  = threadIdx.x;
    const int lane = tid & 31;
    const int wid  = tid >> 5;
    const int bid  = blockIdx.x;          // 0..127
    const int n0 = (bid & 31) * 128;
    const int m0 = (bid >> 5) * 64;
    const int t0  = bid * 2;              // A-share t rows
    const int h0w = bid * 32;             // B-share h rows

    float acc[2][4][4];
#pragma unroll
    for (int i = 0; i < 2; ++i)
#pragma unroll
        for (int j = 0; j < 4; ++j)
#pragma unroll
            for (int k = 0; k < 4; ++k) acc[i][j][k] = 0.f;

    // ---- prep: issue cp.async for chunk c's x slice + W tile into smem ----
    auto issue_prep = [&](int c) {
        const uint32_t xb = sb + XBUF_OFF;
#pragma unroll
        for (int k = 0; k < 8; ++k) {
            const int p = k * 256 + tid;
            const int b = p >> 5, tl = (p >> 4) & 1, seg = p & 15;
            cp16(xb + b * 512 + tl * 256 + seg * 16,
                 &x[(size_t)(b * T + t0 + tl) * Isz + c * 64 + seg * 4]);
        }
        const uint32_t wb = sb + WBUF_OFF;
#pragma unroll
        for (int k = 0; k < 2; ++k) {
            const int p = k * 256 + tid;
            const int row = p >> 3, seg = p & 7;
            cp16(wb + row * 144 + seg * 16,
                 &W[(size_t)(c * 64 + row) * Hsz + h0w + seg * 4]);
        }
        cp_commit();
    };

    // ---- prep: consume staged data -> global A/B, publish flag[c] ----
    auto consume_prep = [&](int c) {
        if (tid < 128) {
            const float* xb = (const float*)(smem + XBUF_OFF);
            const int tl = tid >> 6, il = tid & 63;
            float s = 0.f;
#pragma unroll 16
            for (int b = 0; b < 64; ++b) s += xb[b * 128 + tl * 64 + il];
            const float v = s * (1.0f / (float)Bsz);
            const __nv_bfloat16 hi = __float2bfloat16(v);
            const __nv_bfloat16 lo = __float2bfloat16(v - __bfloat162float(hi));
            const size_t ia = (size_t)(t0 + tl) * Isz + c * 64 + il;
            g_Ahi[ia] = hi;
            g_Alo[ia] = lo;
        }
        {
            const float* wb = (const float*)(smem + WBUF_OFF);
            const int tr = tid >> 5, tc = tid & 31;
#pragma unroll
            for (int jj = 0; jj < 4; ++jj) {
                const int hl = tr + jj * 8;
                const float v0 = wb[(2 * tc) * 36 + hl];
                const float v1 = wb[(2 * tc + 1) * 36 + hl];
                const __nv_bfloat16 h0b = __float2bfloat16(v0);
                const __nv_bfloat16 h1b = __float2bfloat16(v1);
                const __nv_bfloat16 l0b = __float2bfloat16(v0 - __bfloat162float(h0b));
                const __nv_bfloat16 l1b = __float2bfloat16(v1 - __bfloat162float(h1b));
                const uint32_t hp = (uint32_t)__bfloat16_as_ushort(h0b) |
                                    ((uint32_t)__bfloat16_as_ushort(h1b) << 16);
                const uint32_t lp = (uint32_t)__bfloat16_as_ushort(l0b) |
                                    ((uint32_t)__bfloat16_as_ushort(l1b) << 16);
                const size_t o = ((size_t)(h0w + hl) * Isz + c * 64) / 2 + tc;
                reinterpret_cast<uint32_t*>(g_Bhi)[o] = hp;
                reinterpret_cast<uint32_t*>(g_Blo)[o] = lp;
            }
        }
        __threadfence();
        __syncthreads();                       // all reads + stores done
        if (tid == 0) atomicAdd(&g_flag[c], 1);
    };

    auto spin_flag = [&](int c) {
        if (tid == 0) {
            while (ld_acq(&g_flag[c]) < 128) {}
        }
        __syncthreads();
    };

    auto stage_base = [&](int c) -> uint32_t {
        return sb + (uint32_t)(c % NSTAGE) * STAGE_B;
    };

    auto load_chunk = [&](int c) {
        const int k0 = c << 6;
        const uint32_t base = stage_base(c);
#pragma unroll
        for (int i = 0; i < 2; ++i) {
            const int idx = i * 256 + tid;
            const int row = idx >> 3, cc = idx & 7;
            const size_t go = (size_t)(m0 + row) * Isz + k0 + cc * 8;
            const uint32_t so = row * LDA_B + cc * 16;
            cp16(base + so, &g_Ahi[go]);
            cp16(base + A_TILE_B + so, &g_Alo[go]);
        }
#pragma unroll
        for (int i = 0; i < 4; ++i) {
            const int idx = i * 256 + tid;
            const int row = idx >> 3, cc = idx & 7;
            const size_t go = (size_t)(n0 + row) * Isz + k0 + cc * 8;
            const uint32_t so = row * LDA_B + cc * 16;
            cp16(base + 2 * A_TILE_B + so, &g_Bhi[go]);
            cp16(base + 2 * A_TILE_B + B_TILE_B + so, &g_Blo[go]);
        }
        cp_commit();
    };

    const uint32_t a_row_off = (uint32_t)((wid & 1) * 32 + (lane & 15)) * LDA_B;
    const uint32_t b_row_off = (uint32_t)((wid >> 1) * 32 + (lane & 15)) * LDA_B;
    const uint32_t k_half    = (uint32_t)((lane >> 4) << 3) * 2;
    const int wm_off = (wid & 1) * 32;
    const int wn_off = (wid >> 1) * 32;

    // ---- prologue: prep chunks 0..2 fully, issue P3, tiles T0/T1 ----
    issue_prep(0);
    cp_wait<0>(); __syncthreads();
    consume_prep(0);
    issue_prep(1);
    cp_wait<0>(); __syncthreads();
    consume_prep(1);
    issue_prep(2);
    cp_wait<0>(); __syncthreads();
    consume_prep(2);
    issue_prep(3);                     // P3 stays pending
    spin_flag(0); load_chunk(0);       // T0
    spin_flag(1); load_chunk(1);       // T1

    for (int j = 0; j < NCHUNK; ++j) {
        // completes T(j) and P(j+3); leaves newest group(s) pending
        if (j <= 30) cp_wait<1>(); else cp_wait<0>();
        __syncthreads();

        if (j + 3 < NCHUNK) consume_prep(j + 3);   // reads bufs; ends w/ sync
        if (j + 4 < NCHUNK) issue_prep(j + 4);     // overwrites bufs (safe)
        if (j + 2 < NCHUNK) { spin_flag(j + 2); load_chunk(j + 2); }

        const uint32_t base  = stage_base(j);
        const uint32_t ahi_b = base;
        const uint32_t alo_b = base + A_TILE_B;
        const uint32_t bhi_b = base + 2 * A_TILE_B;
        const uint32_t blo_b = bhi_b + B_TILE_B;

        uint32_t ahi[2][2][4], alo[2][2][4], bhi[2][2][4], blo[2][2][4];
        auto ldsm_k = [&](int k16, int bf) {
            const uint32_t kbyte = (uint32_t)(k16 * 16) * 2 + k_half;
            const uint32_t ar = a_row_off + kbyte;
            const uint32_t br = b_row_off + kbyte;
#pragma unroll
            for (int mt = 0; mt < 2; ++mt) {
                LDSM_X4(ahi[bf][mt][0], ahi[bf][mt][1], ahi[bf][mt][2], ahi[bf][mt][3],
                        ahi_b + ar + mt * 16 * LDA_B);
                LDSM_X4(alo[bf][mt][0], alo[bf][mt][1], alo[bf][mt][2], alo[bf][mt][3],
                        alo_b + ar + mt * 16 * LDA_B);
            }
#pragma unroll
            for (int nt2 = 0; nt2 < 2; ++nt2) {
                LDSM_X4(bhi[bf][nt2][0], bhi[bf][nt2][1], bhi[bf][nt2][2], bhi[bf][nt2][3],
                        bhi_b + br + nt2 * 16 * LDA_B);
                LDSM_X4(blo[bf][nt2][0], blo[bf][nt2][1], blo[bf][nt2][2], blo[bf][nt2][3],
                        blo_b + br + nt2 * 16 * LDA_B);
            }
        };

        ldsm_k(0, 0);
#pragma unroll
        for (int k16 = 0; k16 < 4; ++k16) {
            const int cur = k16 & 1;
            if (k16 < 3) ldsm_k(k16 + 1, cur ^ 1);
#pragma unroll
            for (int mt = 0; mt < 2; ++mt)
#pragma unroll
                for (int nt = 0; nt < 4; ++nt) {
                    const int g = nt >> 1, w = nt & 1;
                    MMA_BF16(acc[mt][nt], ahi[cur][mt], bhi[cur][g][w], bhi[cur][g][2 + w]);
                    MMA_BF16(acc[mt][nt], alo[cur][mt], bhi[cur][g][w], bhi[cur][g][2 + w]);
                    MMA_BF16(acc[mt][nt], ahi[cur][mt], blo[cur][g][w], blo[cur][g][2 + w]);
                }
        }
    }

    // epilogue: write g_cur with bias
#pragma unroll
    for (int mt = 0; mt < 2; ++mt) {
#pragma unroll
        for (int nt = 0; nt < 4; ++nt) {
            const int col = n0 + wn_off + nt * 8 + (lane & 3) * 2;
            const float2 bia = *reinterpret_cast<const float2*>(&b_in[col]);
            const int r0 = m0 + wm_off + mt * 16 + (lane >> 2);
            float2 v0, v1;
            v0.x = acc[mt][nt][0] + bia.x;
            v0.y = acc[mt][nt][1] + bia.y;
            v1.x = acc[mt][nt][2] + bia.x;
            v1.y = acc[mt][nt][3] + bia.y;
            *reinterpret_cast<float2*>(&g_cur[(size_t)r0 * Hsz + col]) = v0;
            *reinterpret_cast<float2*>(&g_cur[(size_t)(r0 + 8) * Hsz + col]) = v1;
        }
    }

    // reset flags for the next (graph-replayed) launch: last CTA cleans up.
    __syncthreads();
    if (tid == 0) {
        __threadfence();
        const int d = atomicAdd(&g_done, 1);
        if (d == 127) {
#pragma unroll
            for (int c = 0; c < NCHUNK; ++c) g_flag[c] = 0;
            __threadfence();
            g_done = 0;
        }
    }
}

// ---------------------------------------------------------------------------
// LIF scan: 128 blocks x 32 threads, software-pipelined 16-deep prefetch.
// Also initializes out[] = b_out[] (blocks 0..31) ahead of the GEMV.
// ---------------------------------------------------------------------------
__global__ __launch_bounds__(32) void scan_kernel(const float* __restrict__ m0,
                                                  float* __restrict__ out,
                                                  const float* __restrict__ b_out) {
    const int h = blockIdx.x * 32 + threadIdx.x;
    if (blockIdx.x < Osz / 32) out[h] = b_out[h];

    float m = m0[h];
    float s = 0.f;
    float buf[2][16];
#pragma unroll
    for (int i = 0; i < 16; ++i)
        buf[0][i] = __ldg(&g_cur[(size_t)i * Hsz + h]);

#pragma unroll
    for (int t0 = 0; t0 < T; t0 += 16) {
        const int cur = (t0 >> 4) & 1;
        const int nxt = cur ^ 1;
        if (t0 + 16 < T) {
#pragma unroll
            for (int i = 0; i < 16; ++i)
                buf[nxt][i] = __ldg(&g_cur[(size_t)(t0 + 16 + i) * Hsz + h]);
        }
#pragma unroll
        for (int i = 0; i < 16; ++i) {
            m = DECAY * m + buf[cur][i];
            if (m > THRESHOLD) { s += 1.0f; m = 0.0f; }
        }
    }
    g_agg[h] = s * (1.0f / (float)T);
}

// ---------------------------------------------------------------------------
// Output GEMV (out pre-initialized with bias by scan_kernel)
// ---------------------------------------------------------------------------
#define OUT_OB 128
#define OUT_HB 64

__global__ __launch_bounds__(OUT_OB) void out_gemv_kernel(
    const float* __restrict__ W_out, float* __restrict__ out)
{
    __shared__ float s_agg[OUT_HB];
    const int obase = blockIdx.x * OUT_OB;
    const int hbase = blockIdx.y * OUT_HB;
    const int tid   = threadIdx.x;

    if (tid < OUT_HB) s_agg[tid] = g_agg[hbase + tid];
    __syncthreads();

    const int o = obase + tid;
    const float* __restrict__ Wp = &W_out[(size_t)hbase * Osz + o];
    float acc0 = 0.f, acc1 = 0.f;
#pragma unroll
    for (int hh = 0; hh < OUT_HB; hh += 2) {
        acc0 += s_agg[hh]     * Wp[(size_t)hh * Osz];
        acc1 += s_agg[hh + 1] * Wp[(size_t)(hh + 1) * Osz];
    }
    atomicAdd(&out[o], acc0 + acc1);
}

// ---------------------------------------------------------------------------
extern "C" void kernel_launch(void* const* d_in, const int* in_sizes, int n_in,
                              void* d_out, int out_size) {
    const float* x     = (const float*)d_in[0];  // [B,T,I]
    const float* W_in  = (const float*)d_in[1];  // [I,H]
    const float* b_in  = (const float*)d_in[2];  // [H]
    const float* W_out = (const float*)d_in[3];  // [H,O]
    const float* b_out = (const float*)d_in[4];  // [O]
    const float* m0    = (const float*)d_in[5];  // [H]
    float* out = (float*)d_out;                  // [O]

    // 1) fused prep + GEMM: 128 CTAs (all co-resident; 1/SM by smem)
    cudaFuncSetAttribute(fused_gemm,
                         cudaFuncAttributeMaxDynamicSharedMemorySize,
                         FUSED_SMEM);
    fused_gemm<<<128, 256, FUSED_SMEM>>>(x, W_in, b_in);

    // 2) scan (+ output bias init): 128 blocks x 32 threads
    scan_kernel<<<Hsz / 32, 32>>>(m0, out, b_out);

    // 3) output GEMV: grid (8, 64) = 512 blocks
    dim3 g4(Osz / OUT_OB, Hsz / OUT_HB);
    out_gemv_kernel<<<g4, OUT_OB>>>(W_out, out);
}

// round 13
// speedup vs baseline: 1.4595x; 1.4595x over previous
#include <cuda_runtime.h>
#include <cuda_bf16.h>
#include <cstdint>

#define Bsz 64
#define T   256
#define Isz 2048
#define Hsz 4096
#define Osz 1024

#define THRESHOLD 1.0f
#define DECAY     0.9f

// ---------------- scratch (device globals; no allocation allowed) ----------
__device__ __nv_bfloat16 g_Ahi[T * Isz];     // 1 MB
__device__ __nv_bfloat16 g_Alo[T * Isz];     // 1 MB
__device__ __nv_bfloat16 g_Bhi[Hsz * Isz];   // 16 MB  [N=4096][K=2048] K-major
__device__ __nv_bfloat16 g_Blo[Hsz * Isz];   // 16 MB
__device__ float g_cur[T * Hsz];             // 4 MB
__device__ float g_agg[Hsz];

// ---------------- PTX helpers ----------------------------------------------
__device__ __forceinline__ uint32_t smem_u32(const void* p) {
    uint32_t a;
    asm("{ .reg .u64 t; cvta.to.shared.u64 t, %1; cvt.u32.u64 %0, t; }"
        : "=r"(a) : "l"(p));
    return a;
}
__device__ __forceinline__ void cp16(uint32_t dst, const void* src) {
    asm volatile("cp.async.cg.shared.global [%0], [%1], 16;" :: "r"(dst), "l"(src));
}
__device__ __forceinline__ void cp_commit() {
    asm volatile("cp.async.commit_group;" ::: "memory");
}
template <int N> __device__ __forceinline__ void cp_wait() {
    asm volatile("cp.async.wait_group %0;" :: "n"(N) : "memory");
}
#define LDSM_X4(r0, r1, r2, r3, addr) \
    asm volatile("ldmatrix.sync.aligned.m8n8.x4.shared.b16 {%0,%1,%2,%3}, [%4];" \
                 : "=r"(r0), "=r"(r1), "=r"(r2), "=r"(r3) : "r"(addr))
#define MMA_BF16(d, a, b0, b1) \
    asm volatile("mma.sync.aligned.m16n8k16.row.col.f32.bf16.bf16.f32 " \
                 "{%0,%1,%2,%3}, {%4,%5,%6,%7}, {%8,%9}, {%0,%1,%2,%3};" \
                 : "+f"((d)[0]), "+f"((d)[1]), "+f"((d)[2]), "+f"((d)[3]) \
                 : "r"((a)[0]), "r"((a)[1]), "r"((a)[2]), "r"((a)[3]), \
                   "r"(b0), "r"(b1))

// ---------------------------------------------------------------------------
// 1) Merged prep: blocks [0,512) batch-reduce x -> A hi/lo;
//    blocks [512, 512+4096) transpose+convert W_in -> B hi/lo (packed stores).
// ---------------------------------------------------------------------------
#define RED_BLOCKS 512
__global__ __launch_bounds__(256) void prep_kernel(const float* __restrict__ x,
                                                   const float* __restrict__ W) {
    if (blockIdx.x < RED_BLOCKS) {
        const int idx = blockIdx.x * 256 + threadIdx.x;  // over T*I/4
        const int n4  = (T * Isz) / 4;
        const float4* __restrict__ x4 = reinterpret_cast<const float4*>(x);
        float a[4] = {0.f, 0.f, 0.f, 0.f};
#pragma unroll 16
        for (int b = 0; b < Bsz; ++b) {
            float4 v = x4[(size_t)b * n4 + idx];
            a[0] += v.x; a[1] += v.y; a[2] += v.z; a[3] += v.w;
        }
        const float s = 1.0f / (float)Bsz;
        const int base = idx * 4;
#pragma unroll
        for (int i = 0; i < 4; ++i) {
            float v = a[i] * s;
            __nv_bfloat16 hi = __float2bfloat16(v);
            float rem = v - __bfloat162float(hi);
            g_Ahi[base + i] = hi;
            g_Alo[base + i] = __float2bfloat16(rem);
        }
    } else {
        __shared__ float s[64][33];
        const int bid = blockIdx.x - RED_BLOCKS;       // 0..4095
        const int h0 = (bid & 127) * 32;
        const int i0 = (bid >> 7) * 64;
        const int tc = threadIdx.x & 31;
        const int tr = threadIdx.x >> 5;               // 0..7
#pragma unroll
        for (int j = 0; j < 8; ++j) {
            const int r = tr + j * 8;
            s[r][tc] = W[(size_t)(i0 + r) * Hsz + h0 + tc];
        }
        __syncthreads();
#pragma unroll
        for (int j = 0; j < 4; ++j) {
            const int hl = tr + j * 8;
            const float v0 = s[2 * tc][hl];
            const float v1 = s[2 * tc + 1][hl];
            const __nv_bfloat16 h0b = __float2bfloat16(v0);
            const __nv_bfloat16 h1b = __float2bfloat16(v1);
            const __nv_bfloat16 l0b = __float2bfloat16(v0 - __bfloat162float(h0b));
            const __nv_bfloat16 l1b = __float2bfloat16(v1 - __bfloat162float(h1b));
            const uint32_t hp = (uint32_t)__bfloat16_as_ushort(h0b) |
                                ((uint32_t)__bfloat16_as_ushort(h1b) << 16);
            const uint32_t lp = (uint32_t)__bfloat16_as_ushort(l0b) |
                                ((uint32_t)__bfloat16_as_ushort(l1b) << 16);
            const size_t o = ((size_t)(h0 + hl) * Isz + i0) / 2 + tc;
            reinterpret_cast<uint32_t*>(g_Bhi)[o] = hp;
            reinterpret_cast<uint32_t*>(g_Blo)[o] = lp;
        }
    }
}

// ---------------------------------------------------------------------------
// 2) HMMA bf16 GEMM, fused 3-product hi/lo compensation per k-chunk:
//    acc += Ahi*Bhi + Alo*Bhi + Ahi*Blo   (per BK=128 chunk, tiles loaded once)
//    CTA 64(M)x128(N), 8 warps of 32x32, 2-stage cp.async pipeline (BK=128),
//    double-buffered LDSM fragments, 1 barrier per chunk. MMA-issue bound.
// ---------------------------------------------------------------------------
#define LDA_B 272                        // 128 bf16 (256B) + 16B pad row stride
#define A_TILE_B (64 * LDA_B)            // 17408
#define B_TILE_B (128 * LDA_B)           // 34816
#define STAGE_B  (2 * A_TILE_B + 2 * B_TILE_B)  // 104448
#define NSTAGE 2
#define GEMM_SMEM (NSTAGE * STAGE_B)     // 208896
#define NCHUNK 16                        // 2048 / 128

__global__ __launch_bounds__(256, 1) void gemm_hmma(const float* __restrict__ b_in) {
    extern __shared__ char smem[];
    const uint32_t sb = smem_u32(smem);
    const int tid  = threadIdx.x;
    const int lane = tid & 31;
    const int wid  = tid >> 5;
    const int m0 = blockIdx.y * 64;
    const int n0 = blockIdx.x * 128;

    const int wm_off = (wid & 1) * 32;
    const int wn_off = (wid >> 1) * 32;

    float acc[2][4][4];
#pragma unroll
    for (int i = 0; i < 2; ++i)
#pragma unroll
        for (int j = 0; j < 4; ++j)
#pragma unroll
            for (int k = 0; k < 4; ++k) acc[i][j][k] = 0.f;

    auto stage_base = [&](int c) -> uint32_t {
        return sb + (uint32_t)(c & 1) * STAGE_B;
    };

    // stage layout: [Ahi 17408][Alo 17408][Bhi 34816][Blo 34816]
    auto load_chunk = [&](int c) {
        const int k0 = c << 7;           // 128 k per chunk
        const uint32_t base = stage_base(c);
#pragma unroll
        for (int i = 0; i < 4; ++i) {
            const int idx = i * 256 + tid;
            const int row = idx >> 4, cc = idx & 15;
            const size_t go = (size_t)(m0 + row) * Isz + k0 + cc * 8;
            const uint32_t so = row * LDA_B + cc * 16;
            cp16(base + so, &g_Ahi[go]);
            cp16(base + A_TILE_B + so, &g_Alo[go]);
        }
#pragma unroll
        for (int i = 0; i < 8; ++i) {
            const int idx = i * 256 + tid;
            const int row = idx >> 4, cc = idx & 15;
            const size_t go = (size_t)(n0 + row) * Isz + k0 + cc * 8;
            const uint32_t so = row * LDA_B + cc * 16;
            cp16(base + 2 * A_TILE_B + so, &g_Bhi[go]);
            cp16(base + 2 * A_TILE_B + B_TILE_B + so, &g_Blo[go]);
        }
        cp_commit();
    };

    const uint32_t a_row_off = (uint32_t)(wm_off + (lane & 15)) * LDA_B;
    const uint32_t b_row_off = (uint32_t)(wn_off + (lane & 15)) * LDA_B;
    const uint32_t k_half    = (uint32_t)((lane >> 4) << 3) * 2;  // 0 or 16B

    load_chunk(0);

    for (int j = 0; j < NCHUNK; ++j) {
        cp_wait<0>();       // only load(j) pending here -> wait for it
        __syncthreads();    // all warps done computing stage (j-1)&1

        if (j + 1 < NCHUNK) load_chunk(j + 1);  // writes stage (j+1)&1: safe now

        const uint32_t base  = stage_base(j);
        const uint32_t ahi_b = base;
        const uint32_t alo_b = base + A_TILE_B;
        const uint32_t bhi_b = base + 2 * A_TILE_B;
        const uint32_t blo_b = bhi_b + B_TILE_B;

        uint32_t ahi[2][2][4], alo[2][2][4], bhi[2][2][4], blo[2][2][4];
        auto ldsm_k = [&](int k16, int bf) {
            const uint32_t kbyte = (uint32_t)(k16 * 16) * 2 + k_half;
            const uint32_t ar = a_row_off + kbyte;
            const uint32_t br = b_row_off + kbyte;
#pragma unroll
            for (int mt = 0; mt < 2; ++mt) {
                LDSM_X4(ahi[bf][mt][0], ahi[bf][mt][1], ahi[bf][mt][2], ahi[bf][mt][3],
                        ahi_b + ar + mt * 16 * LDA_B);
                LDSM_X4(alo[bf][mt][0], alo[bf][mt][1], alo[bf][mt][2], alo[bf][mt][3],
                        alo_b + ar + mt * 16 * LDA_B);
            }
#pragma unroll
            for (int nt2 = 0; nt2 < 2; ++nt2) {
                LDSM_X4(bhi[bf][nt2][0], bhi[bf][nt2][1], bhi[bf][nt2][2], bhi[bf][nt2][3],
                        bhi_b + br + nt2 * 16 * LDA_B);
                LDSM_X4(blo[bf][nt2][0], blo[bf][nt2][1], blo[bf][nt2][2], blo[bf][nt2][3],
                        blo_b + br + nt2 * 16 * LDA_B);
            }
        };

        ldsm_k(0, 0);
#pragma unroll
        for (int k16 = 0; k16 < 8; ++k16) {
            const int cur = k16 & 1;
            if (k16 < 7) ldsm_k(k16 + 1, cur ^ 1);
#pragma unroll
            for (int mt = 0; mt < 2; ++mt)
#pragma unroll
                for (int nt = 0; nt < 4; ++nt) {
                    const int g = nt >> 1, w = nt & 1;
                    MMA_BF16(acc[mt][nt], ahi[cur][mt], bhi[cur][g][w], bhi[cur][g][2 + w]);
                    MMA_BF16(acc[mt][nt], alo[cur][mt], bhi[cur][g][w], bhi[cur][g][2 + w]);
                    MMA_BF16(acc[mt][nt], ahi[cur][mt], blo[cur][g][w], blo[cur][g][2 + w]);
                }
        }
    }

    // epilogue: write g_cur with bias
#pragma unroll
    for (int mt = 0; mt < 2; ++mt) {
#pragma unroll
        for (int nt = 0; nt < 4; ++nt) {
            const int col = n0 + wn_off + nt * 8 + (lane & 3) * 2;
            const float2 bia = *reinterpret_cast<const float2*>(&b_in[col]);
            const int r0 = m0 + wm_off + mt * 16 + (lane >> 2);
            float2 v0, v1;
            v0.x = acc[mt][nt][0] + bia.x;
            v0.y = acc[mt][nt][1] + bia.y;
            v1.x = acc[mt][nt][2] + bia.x;
            v1.y = acc[mt][nt][3] + bia.y;
            *reinterpret_cast<float2*>(&g_cur[(size_t)r0 * Hsz + col]) = v0;
            *reinterpret_cast<float2*>(&g_cur[(size_t)(r0 + 8) * Hsz + col]) = v1;
        }
    }
}

// ---------------------------------------------------------------------------
// 3) LIF scan: 128 blocks x 32 threads, software-pipelined 16-deep prefetch.
//    Also initializes out[] = b_out[] (blocks 0..31) ahead of the GEMV.
// ---------------------------------------------------------------------------
__global__ __launch_bounds__(32) void scan_kernel(const float* __restrict__ m0,
                                                  float* __restrict__ out,
                                                  const float* __restrict__ b_out) {
    const int h = blockIdx.x * 32 + threadIdx.x;
    if (blockIdx.x < Osz / 32) out[h] = b_out[h];

    float m = m0[h];
    float s = 0.f;
    float buf[2][16];
#pragma unroll
    for (int i = 0; i < 16; ++i)
        buf[0][i] = __ldg(&g_cur[(size_t)i * Hsz + h]);

#pragma unroll
    for (int t0 = 0; t0 < T; t0 += 16) {
        const int cur = (t0 >> 4) & 1;
        const int nxt = cur ^ 1;
        if (t0 + 16 < T) {
#pragma unroll
            for (int i = 0; i < 16; ++i)
                buf[nxt][i] = __ldg(&g_cur[(size_t)(t0 + 16 + i) * Hsz + h]);
        }
#pragma unroll
        for (int i = 0; i < 16; ++i) {
            m = DECAY * m + buf[cur][i];
            if (m > THRESHOLD) { s += 1.0f; m = 0.0f; }
        }
    }
    g_agg[h] = s * (1.0f / (float)T);
}

// ---------------------------------------------------------------------------
// 4) Output GEMV (out pre-initialized with bias by scan_kernel)
//    512 blocks x 128 threads, 64 h per block, explicit 16-deep load batches
//    so ~16 LDGs stay in flight (R11 version was reg-limited to ~6).
// ---------------------------------------------------------------------------
#define OUT_OB 128
#define OUT_HB 64

__global__ __launch_bounds__(OUT_OB) void out_gemv_kernel(
    const float* __restrict__ W_out, float* __restrict__ out)
{
    __shared__ float s_agg[OUT_HB];
    const int obase = blockIdx.x * OUT_OB;
    const int hbase = blockIdx.y * OUT_HB;
    const int tid   = threadIdx.x;

    if (tid < OUT_HB) s_agg[tid] = g_agg[hbase + tid];
    __syncthreads();

    const int o = obase + tid;
    const float* __restrict__ Wp = &W_out[(size_t)hbase * Osz + o];
    float acc0 = 0.f, acc1 = 0.f;
#pragma unroll
    for (int g = 0; g < 4; ++g) {
        float w[16];
#pragma unroll
        for (int i = 0; i < 16; ++i)
            w[i] = Wp[(size_t)(g * 16 + i) * Osz];
#pragma unroll
        for (int i = 0; i < 16; i += 2) {
            acc0 += s_agg[g * 16 + i]     * w[i];
            acc1 += s_agg[g * 16 + i + 1] * w[i + 1];
        }
    }
    atomicAdd(&out[o], acc0 + acc1);
}

// ---------------------------------------------------------------------------
extern "C" void kernel_launch(void* const* d_in, const int* in_sizes, int n_in,
                              void* d_out, int out_size) {
    const float* x     = (const float*)d_in[0];  // [B,T,I]
    const float* W_in  = (const float*)d_in[1];  // [I,H]
    const float* b_in  = (const float*)d_in[2];  // [H]
    const float* W_out = (const float*)d_in[3];  // [H,O]
    const float* b_out = (const float*)d_in[4];  // [O]
    const float* m0    = (const float*)d_in[5];  // [H]
    float* out = (float*)d_out;                  // [O]

    // 1) merged reduce + transpose/convert
    prep_kernel<<<RED_BLOCKS + (Hsz / 32) * (Isz / 64), 256>>>(x, W_in);

    // 2) HMMA tensor-core GEMM: grid (32, 4) = 128 CTAs, BK=128, 2 stages
    cudaFuncSetAttribute(gemm_hmma,
                         cudaFuncAttributeMaxDynamicSharedMemorySize,
                         GEMM_SMEM);
    dim3 gg(Hsz / 128, T / 64);
    gemm_hmma<<<gg, 256, GEMM_SMEM>>>(b_in);

    // 3) scan (+ output bias init): 128 blocks x 32 threads
    scan_kernel<<<Hsz / 32, 32>>>(m0, out, b_out);

    // 4) output GEMV: grid (8, 64) = 512 blocks
    dim3 g4(Osz / OUT_OB, Hsz / OUT_HB);
    out_gemv_kernel<<<g4, OUT_OB>>>(W_out, out);
}